// round 7
// baseline (speedup 1.0000x reference)
#include <cuda_runtime.h>
#include <cuda_bf16.h>
#include <math.h>
#include <stdint.h>

#define NN 2048
#define BB 256
#define DD 512
#define MAXIT 300

// ---- solve: 16 m-tiles x 8 k-splits, W chunk resident in SMEM --------------
#define SB 128
#define MT 128
#define KS 256
#define O_WBYTES 131072
#define BSTG 40960       // one B stage: 256 j x 80B x 2 prec
#define BPREC 20480
#define DYN_SMEM (O_WBYTES + 2*BSTG + 256)

// ---- build_w tiling ---------------------------------------------------------
#define WNSTG 3
#define WMAT (128*128)
#define WSTG (4*WMAT)
#define WDYN (WNSTG*WSTG + 128)
#define KC 64
#define NKC (NN/KC)

__device__ __nv_bfloat16 g_Whi[NN*NN];
__device__ __nv_bfloat16 g_Wlo[NN*NN];
__device__ __nv_bfloat16 g_Athi[NN*NN];
__device__ __nv_bfloat16 g_Atlo[NN*NN];
__device__ float         g_Vx[NN*BB];        // [i][j]
__device__ float         g_zf2[2][NN*BB];    // fp32 z, [i][j], ping-pong
__device__ __nv_bfloat16 g_zbh[2][BB*NN];    // z hi split, [j][k]
__device__ __nv_bfloat16 g_zbl[2][BB*NN];
__device__ float         g_part[(long)SB*MT*BB];
__device__ double g_nd[3][2];
__device__ int g_pcnt[16];   // partial-ready per m-group (monotone)
__device__ int g_zcnt[16];   // z-ready per m-group (monotone)
__device__ int g_ncnt;       // norm contributions (monotone)

__device__ __forceinline__ uint32_t smem_u32(const void* p) {
    uint32_t a;
    asm("{ .reg .u64 t; cvta.to.shared.u64 t, %1; cvt.u32.u64 %0, t; }" : "=r"(a) : "l"(p));
    return a;
}
__device__ __forceinline__ void cp16(uint32_t dst, const void* src) {
    asm volatile("cp.async.cg.shared.global [%0], [%1], 16;" :: "r"(dst), "l"(src) : "memory");
}
#define CP_COMMIT() asm volatile("cp.async.commit_group;" ::: "memory")
#define CP_WAIT(n)  asm volatile("cp.async.wait_group %0;" :: "n"(n) : "memory")
__device__ __forceinline__ void ldsm4(uint32_t* r, uint32_t a) {
    asm volatile("ldmatrix.sync.aligned.m8n8.x4.shared.b16 {%0,%1,%2,%3}, [%4];"
                 : "=r"(r[0]), "=r"(r[1]), "=r"(r[2]), "=r"(r[3]) : "r"(a));
}
__device__ __forceinline__ void mma16816(float* c, const uint32_t* a, uint32_t b0, uint32_t b1) {
    asm volatile("mma.sync.aligned.m16n8k16.row.col.f32.bf16.bf16.f32 "
                 "{%0,%1,%2,%3}, {%4,%5,%6,%7}, {%8,%9}, {%0,%1,%2,%3};"
                 : "+f"(c[0]), "+f"(c[1]), "+f"(c[2]), "+f"(c[3])
                 : "r"(a[0]), "r"(a[1]), "r"(a[2]), "r"(a[3]), "r"(b0), "r"(b1));
}

__global__ void init_kernel() {
    int idx = blockIdx.x * blockDim.x + threadIdx.x;
    if (idx < BB * NN) {
        g_zbh[0][idx] = __float2bfloat16(0.0f);
        g_zbl[0][idx] = __float2bfloat16(0.0f);
        g_zf2[0][idx] = 0.0f;
    }
    if (idx < 16) { g_pcnt[idx] = 0; g_zcnt[idx] = 0; }
    if (idx == 0) {
        for (int i = 0; i < 3; i++) { g_nd[i][0] = 0.0; g_nd[i][1] = 0.0; }
        g_ncnt = 0;
    }
}

// At[i][k] = A[k][i], split bf16 hi/lo
__global__ void __launch_bounds__(256) split_at_kernel(const float* __restrict__ A) {
    __shared__ float t[32][33];
    const int i0 = blockIdx.x * 32, k0 = blockIdx.y * 32;
    const int lx = threadIdx.x & 31, ly = threadIdx.x >> 5;
#pragma unroll
    for (int r = 0; r < 32; r += 8)
        t[ly + r][lx] = A[(long)(k0 + ly + r) * NN + i0 + lx];
    __syncthreads();
#pragma unroll
    for (int r = 0; r < 32; r += 8) {
        const float v = t[lx][ly + r];
        const long o = (long)(i0 + ly + r) * NN + k0 + lx;
        __nv_bfloat16 hi = __float2bfloat16_rn(v);
        g_Athi[o] = hi;
        g_Atlo[o] = __float2bfloat16_rn(v - __bfloat162float(hi));
    }
}

// W = (1-m)I - At At^T + S - S^T  (bf16x3 mma), tile 128x128
__global__ void __launch_bounds__(256, 1) build_w_mma_kernel(const float* __restrict__ S,
                                                             const float* __restrict__ m_raw) {
    extern __shared__ __align__(16) char dsm[];
    const uint32_t sbase = (smem_u32(dsm) + 127u) & ~127u;
    const int tid = threadIdx.x, l = tid & 31, warp = tid >> 5;
    const int i0 = blockIdx.x * 128, j0 = blockIdx.y * 128;
    const int wm = (warp >> 2) * 64, wn = (warp & 3) * 32;
    const int r7 = l & 7;
    const int rowA = wm + r7 + ((l >> 3) & 1) * 8;
    const int kgA = (l >> 4) & 1;
    const int rowBb = wn + r7 + ((l >> 4) & 1) * 8;
    const int kgB = (l >> 3) & 1;
    const int ld_r = tid >> 3, ld_c = tid & 7;

    float c[4][4][4];
#pragma unroll
    for (int f = 0; f < 4; f++)
#pragma unroll
        for (int g = 0; g < 4; g++)
#pragma unroll
            for (int q = 0; q < 4; q++) c[f][g][q] = 0.0f;

#define W_LOAD(stg, k0v) do {                                                 \
    const uint32_t sb_ = sbase + (stg) * WSTG;                                \
    _Pragma("unroll")                                                         \
    for (int rep = 0; rep < 4; rep++) {                                       \
        const int r_ = ld_r + rep * 32;                                       \
        const uint32_t d_ = (uint32_t)r_ * 128 + ((uint32_t)(ld_c ^ (r_ & 7)) << 4); \
        const long ga_ = (long)(i0 + r_) * NN + (k0v) + ld_c * 8;             \
        const long gb_ = (long)(j0 + r_) * NN + (k0v) + ld_c * 8;             \
        cp16(sb_ + 0*WMAT + d_, g_Athi + ga_);                                \
        cp16(sb_ + 1*WMAT + d_, g_Atlo + ga_);                                \
        cp16(sb_ + 2*WMAT + d_, g_Athi + gb_);                                \
        cp16(sb_ + 3*WMAT + d_, g_Atlo + gb_);                                \
    } } while (0)

#pragma unroll
    for (int s = 0; s < WNSTG - 1; s++) { W_LOAD(s, s * KC); CP_COMMIT(); }

    for (int kc = 0; kc < NKC; kc++) {
        CP_WAIT(WNSTG - 2);
        __syncthreads();
        if (kc + WNSTG - 1 < NKC) W_LOAD((kc + WNSTG - 1) % WNSTG, (kc + WNSTG - 1) * KC);
        CP_COMMIT();
        const uint32_t sb = sbase + (kc % WNSTG) * WSTG;
#pragma unroll
        for (int s4 = 0; s4 < 4; s4++) {
            const int kg0 = s4 * 2;
            const uint32_t swA = (uint32_t)((kg0 + kgA) ^ r7) << 4;
            const uint32_t swB = (uint32_t)((kg0 + kgB) ^ r7) << 4;
            uint32_t ah[4][4], al[4][4], bh[2][4], bl[2][4];
#pragma unroll
            for (int f = 0; f < 4; f++) {
                ldsm4(ah[f], sb + 0*WMAT + (uint32_t)(rowA + f * 16) * 128 + swA);
                ldsm4(al[f], sb + 1*WMAT + (uint32_t)(rowA + f * 16) * 128 + swA);
            }
#pragma unroll
            for (int g2 = 0; g2 < 2; g2++) {
                ldsm4(bh[g2], sb + 2*WMAT + (uint32_t)(rowBb + g2 * 16) * 128 + swB);
                ldsm4(bl[g2], sb + 3*WMAT + (uint32_t)(rowBb + g2 * 16) * 128 + swB);
            }
#pragma unroll
            for (int f = 0; f < 4; f++)
#pragma unroll
                for (int g2 = 0; g2 < 2; g2++) {
                    mma16816(c[f][g2*2+0], ah[f], bh[g2][0], bh[g2][1]);
                    mma16816(c[f][g2*2+1], ah[f], bh[g2][2], bh[g2][3]);
                    mma16816(c[f][g2*2+0], ah[f], bl[g2][0], bl[g2][1]);
                    mma16816(c[f][g2*2+1], ah[f], bl[g2][2], bl[g2][3]);
                    mma16816(c[f][g2*2+0], al[f], bh[g2][0], bh[g2][1]);
                    mma16816(c[f][g2*2+1], al[f], bh[g2][2], bh[g2][3]);
                }
        }
    }
#undef W_LOAD

    const float m = log1pf(expf(m_raw[0]));
    const float omm = 1.0f - m;
#pragma unroll
    for (int f = 0; f < 4; f++)
#pragma unroll
        for (int g = 0; g < 4; g++)
#pragma unroll
            for (int h = 0; h < 2; h++) {
                const int i = i0 + wm + f * 16 + h * 8 + (l >> 2);
                const int j = j0 + wn + g * 8 + (l & 3) * 2;
                float2 sij = *(const float2*)&S[(long)i * NN + j];
                float w0 = -c[f][g][h*2+0] + sij.x - S[(long)j * NN + i];
                float w1 = -c[f][g][h*2+1] + sij.y - S[(long)(j + 1) * NN + i];
                if (i == j) w0 += omm;
                if (i == j + 1) w1 += omm;
                __nv_bfloat16 h0 = __float2bfloat16_rn(w0);
                __nv_bfloat16 h1 = __float2bfloat16_rn(w1);
                *(__nv_bfloat162*)&g_Whi[(long)i * NN + j] = __halves2bfloat162(h0, h1);
                *(__nv_bfloat162*)&g_Wlo[(long)i * NN + j] = __halves2bfloat162(
                    __float2bfloat16_rn(w0 - __bfloat162float(h0)),
                    __float2bfloat16_rn(w1 - __bfloat162float(h1)));
            }
}

#define TMW 64
#define KTW 16
#define PADW 68
__global__ void __launch_bounds__(256) build_vx_kernel(const float* __restrict__ U,
                                                       const float* __restrict__ b,
                                                       const float* __restrict__ x) {
    __shared__ __align__(16) float Us[KTW][PADW];
    __shared__ __align__(16) float Xs[KTW][PADW];
    const int i0 = blockIdx.x * TMW, j0 = blockIdx.y * TMW;
    const int tx = threadIdx.x & 15, ty = threadIdx.x >> 4;
    float acc[4][4];
#pragma unroll
    for (int a = 0; a < 4; a++)
#pragma unroll
        for (int cc = 0; cc < 4; cc++) acc[a][cc] = 0.0f;
    for (int k0 = 0; k0 < DD; k0 += KTW) {
#pragma unroll
        for (int t = threadIdx.x; t < KTW * TMW; t += 256) {
            int rr = t >> 4, cc = t & 15;
            Us[cc][rr] = U[(i0 + rr) * DD + k0 + cc];
            Xs[cc][rr] = x[(j0 + rr) * DD + k0 + cc];
        }
        __syncthreads();
#pragma unroll
        for (int k = 0; k < KTW; k++) {
            float4 av = *(const float4*)&Us[k][ty * 4];
            float4 bv = *(const float4*)&Xs[k][tx * 4];
            float am[4] = {av.x, av.y, av.z, av.w};
            float bn[4] = {bv.x, bv.y, bv.z, bv.w};
#pragma unroll
            for (int mi = 0; mi < 4; mi++)
#pragma unroll
                for (int ni = 0; ni < 4; ni++) acc[mi][ni] += am[mi] * bn[ni];
        }
        __syncthreads();
    }
#pragma unroll
    for (int mi = 0; mi < 4; mi++) {
        const int i = i0 + ty * 4 + mi;
        const float bi = b[i];
#pragma unroll
        for (int ni = 0; ni < 4; ni++)
            g_Vx[i * BB + j0 + tx * 4 + ni] = acc[mi][ni] + bi;
    }
}

// ---------------- persistent split-K solver, loose sync ---------------------
__global__ void __launch_bounds__(256, 1) solve_kernel(float* __restrict__ out) {
    extern __shared__ __align__(16) char dsm[];
    const uint32_t raw = smem_u32(dsm);
    const uint32_t sbase = (raw + 127u) & ~127u;
    const uint32_t O_W = sbase;
    const uint32_t O_B = sbase + O_WBYTES;

    __shared__ float sredD[8], sredN[8];
    __shared__ int s_stop;

    const int tid = threadIdx.x, l = tid & 31, warp = tid >> 5;
    const int bm = blockIdx.x >> 3;       // 0..15 m-tile
    const int ks = blockIdx.x & 7;        // 0..7 k-split
    const int i0 = bm * MT;
    const int kbase = ks * KS;
    const int wm = (warp >> 1) * 32;
    const int wn = (warp & 1) * 128;
    const int r7 = l & 7;
    const int selA = (l >> 4) & 1, rA8 = ((l >> 3) & 1) * 8;
    const int selB = (l >> 3) & 1, rB8 = ((l >> 4) & 1) * 8;

    // ---- load resident W chunk (once) ----
#pragma unroll
    for (int r = 0; r < 32; r++) {
        const int idx = tid + r * 256;
        const int prec = idx >> 12;
        const int rem = idx & 4095;
        const int m = rem >> 5, kc = rem & 31;
        const __nv_bfloat16* src =
            (prec ? g_Wlo : g_Whi) + (long)(i0 + m) * NN + kbase + kc * 8;
        const uint32_t dst = O_W + (uint32_t)prec * 65536u + (uint32_t)(kc >> 3) * 16384u +
                             (uint32_t)m * 128u + ((uint32_t)((kc & 7) ^ (m & 7)) << 4);
        cp16(dst, src);
    }
    CP_COMMIT(); CP_WAIT(0); __syncthreads();

    const int erow = i0 + (tid >> 1);
    const int jcol = ks * 32 + (tid & 1) * 16;

    int it = 0;

#define B_LOAD(s, zhp, zlp) do {                                              \
    const uint32_t bst_ = O_B + (uint32_t)((s) & 1) * BSTG;                   \
    _Pragma("unroll")                                                         \
    for (int r_ = 0; r_ < 8; r_++) {                                          \
        const int idx_ = tid + r_ * 256;                                      \
        const int prec_ = idx_ >> 10;                                         \
        const int rem_ = idx_ & 1023;                                         \
        const int j_ = rem_ >> 2, c_ = rem_ & 3;                              \
        const __nv_bfloat16* src_ =                                           \
            (prec_ ? (zlp) : (zhp)) + (long)j_ * NN + kbase + (s) * 32 + c_ * 8; \
        cp16(bst_ + (uint32_t)prec_ * BPREC + (uint32_t)j_ * 80u +            \
             (uint32_t)c_ * 16u, src_);                                       \
    } } while (0)

    while (1) {
        it++;
        const int pb_idx = (it - 1) & 1;   // z(it-1) buffers
        const __nv_bfloat16* __restrict__ zh = g_zbh[pb_idx];
        const __nv_bfloat16* __restrict__ zl = g_zbl[pb_idx];

        // ---- wait for producers of our k-range (z(it-1) ready) ----
        if (it > 1) {
            if (tid == 0) {
                const int need = 8 * (it - 1);
                while (*(volatile int*)&g_zcnt[2 * ks] < need) { }
                while (*(volatile int*)&g_zcnt[2 * ks + 1] < need) { }
                __threadfence();
            }
            __syncthreads();
        }

        float c[2][8][2][4];
#pragma unroll
        for (int f = 0; f < 2; f++)
#pragma unroll
            for (int g = 0; g < 8; g++)
#pragma unroll
                for (int q = 0; q < 8; q++) c[f][g][q >> 2][q & 3] = 0.0f;

        B_LOAD(0, zh, zl); CP_COMMIT();

        for (int s = 0; s < 8; s++) {
            CP_WAIT(0);
            __syncthreads();
            if (s < 7) { B_LOAD(s + 1, zh, zl); }
            CP_COMMIT();

            const uint32_t bst = O_B + (uint32_t)(s & 1) * BSTG;
            const uint32_t wkb = O_W + (uint32_t)(s >> 1) * 16384u;
            const int lc0 = (s & 1) * 4;
#pragma unroll
            for (int h = 0; h < 2; h++) {
                uint32_t ah[2][4], al[2][4];
#pragma unroll
                for (int f = 0; f < 2; f++) {
                    const int rowA = wm + f * 16 + r7 + rA8;
                    const uint32_t lc = (uint32_t)((lc0 + 2 * h + selA) ^ r7) << 4;
                    const uint32_t aaddr = wkb + (uint32_t)rowA * 128u + lc;
                    ldsm4(ah[f], aaddr);
                    ldsm4(al[f], aaddr + 65536u);
                }
#pragma unroll
                for (int g = 0; g < 8; g++) {
                    const int rowB = wn + g * 16 + r7 + rB8;
                    const uint32_t baddr = bst + (uint32_t)rowB * 80u +
                                           (uint32_t)(2 * h + selB) * 16u;
                    uint32_t bh[4], bl[4];
                    ldsm4(bh, baddr);
                    ldsm4(bl, baddr + BPREC);
#pragma unroll
                    for (int f = 0; f < 2; f++) {
                        mma16816(c[f][g][0], ah[f], bh[0], bh[1]);
                        mma16816(c[f][g][1], ah[f], bh[2], bh[3]);
                        mma16816(c[f][g][0], ah[f], bl[0], bl[1]);
                        mma16816(c[f][g][1], ah[f], bl[2], bl[3]);
                        mma16816(c[f][g][0], al[f], bh[0], bh[1]);
                        mma16816(c[f][g][1], al[f], bh[2], bh[3]);
                    }
                }
            }
        }

        // ---- write fp32 partials, signal group ----
        {
            float* const pb = g_part + (long)blockIdx.x * (MT * BB);
#pragma unroll
            for (int f = 0; f < 2; f++)
#pragma unroll
                for (int g = 0; g < 8; g++)
#pragma unroll
                    for (int n8 = 0; n8 < 2; n8++) {
                        const int row = wm + f * 16 + (l >> 2);
                        const int col = wn + g * 16 + n8 * 8 + (l & 3) * 2;
                        float2 v0, v1;
                        v0.x = c[f][g][n8][0]; v0.y = c[f][g][n8][1];
                        v1.x = c[f][g][n8][2]; v1.y = c[f][g][n8][3];
                        *(float2*)&pb[row * BB + col] = v0;
                        *(float2*)&pb[(row + 8) * BB + col] = v1;
                    }
        }
        __syncthreads();
        if (tid == 0) {
            __threadfence();
            atomicAdd(&g_pcnt[bm], 1);
            while (*(volatile int*)&g_pcnt[bm] < 8 * it) { }
            __threadfence();
        }
        __syncthreads();

        // ---- epilogue: reduce 8 partials, relu update, write z(it) ----
        float acc[16];
#pragma unroll
        for (int t = 0; t < 16; t++) acc[t] = 0.0f;
        {
            const int roff = (tid >> 1) * BB + jcol;
#pragma unroll
            for (int p = 0; p < 8; p++) {
                const float* pp = g_part + (long)(bm * 8 + p) * (MT * BB) + roff;
#pragma unroll
                for (int q = 0; q < 4; q++) {
                    float4 v = *(const float4*)&pp[q * 4];
                    acc[q * 4 + 0] += v.x; acc[q * 4 + 1] += v.y;
                    acc[q * 4 + 2] += v.z; acc[q * 4 + 3] += v.w;
                }
            }
        }
        float d2 = 0.0f, n2 = 0.0f;
        {
            const float* const zfo = g_zf2[pb_idx] + (long)erow * BB + jcol;
            float* const zfn = g_zf2[it & 1] + (long)erow * BB + jcol;
            const float* const vxp = g_Vx + (long)erow * BB + jcol;
            __nv_bfloat16* const zhn = g_zbh[it & 1];
            __nv_bfloat16* const zln = g_zbl[it & 1];
#pragma unroll
            for (int t = 0; t < 16; t++) {
                const float zv = zfo[t];
                float v = 0.9f * zv + 0.1f * (acc[t] + vxp[t]);
                float r = v > 0.0f ? v : 0.0f;
                zfn[t] = r;
                const float dd = r - zv;
                d2 += dd * dd;
                n2 += zv * zv;
                __nv_bfloat16 hi = __float2bfloat16_rn(r);
                const long go = (long)(jcol + t) * NN + erow;
                zhn[go] = hi;
                zln[go] = __float2bfloat16_rn(r - __bfloat162float(hi));
            }
        }
        __syncthreads();
        if (tid == 0) {
            __threadfence();
            atomicAdd(&g_zcnt[bm], 1);   // z(it) for our m-rows published
        }

        // ---- norms + delayed global decision ----
#pragma unroll
        for (int off = 16; off; off >>= 1) {
            d2 += __shfl_xor_sync(0xffffffffu, d2, off);
            n2 += __shfl_xor_sync(0xffffffffu, n2, off);
        }
        if (l == 0) { sredD[warp] = d2; sredN[warp] = n2; }
        __syncthreads();
        const int nb = it % 3;
        if (tid == 0) {
            double Dd = 0.0, Nd = 0.0;
#pragma unroll
            for (int w = 0; w < 8; w++) { Dd += (double)sredD[w]; Nd += (double)sredN[w]; }
            atomicAdd(&g_nd[nb][0], Dd);
            atomicAdd(&g_nd[nb][1], Nd);
            __threadfence();
            const int old = atomicAdd(&g_ncnt, 1);
            while (*(volatile int*)&g_ncnt < 128 * it) { }
            __threadfence();
            const double Dt = *(volatile double*)&g_nd[nb][0];
            const double Nt = *(volatile double*)&g_nd[nb][1];
            const double err = sqrt(Dt) / (sqrt(Nt) + 1e-12);
            if (old == 128 * it - 1) {       // last arriver resets future buffer
                const int rb = (it + 2) % 3;
                *(volatile double*)&g_nd[rb][0] = 0.0;
                *(volatile double*)&g_nd[rb][1] = 0.0;
                __threadfence();
            }
            s_stop = (it >= MAXIT || err < 1e-4) ? 1 : 0;
        }
        __syncthreads();
        if (s_stop) break;
    }
#undef B_LOAD

    // final: copy owned fp32 z(it) to out
    {
        const float* const zfp = g_zf2[it & 1] + (long)erow * BB + jcol;
        float* const op = out + (long)erow * BB + jcol;
#pragma unroll
        for (int q = 0; q < 4; q++)
            *(float4*)&op[q * 4] = *(const float4*)&zfp[q * 4];
    }
}

extern "C" void kernel_launch(void* const* d_in, const int* in_sizes, int n_in,
                              void* d_out, int out_size) {
    const float* A     = (const float*)d_in[0];
    const float* S     = (const float*)d_in[1];
    const float* m_raw = (const float*)d_in[2];
    const float* U     = (const float*)d_in[3];
    const float* b     = (const float*)d_in[4];
    const float* x     = (const float*)d_in[5];
    float* out = (float*)d_out;

    cudaFuncSetAttribute(solve_kernel, cudaFuncAttributeMaxDynamicSharedMemorySize, DYN_SMEM);
    cudaFuncSetAttribute(build_w_mma_kernel, cudaFuncAttributeMaxDynamicSharedMemorySize, WDYN);

    init_kernel<<<(BB * NN + 255) / 256, 256>>>();
    dim3 gt(NN / 32, NN / 32);
    split_at_kernel<<<gt, 256>>>(A);
    dim3 gw(NN / 128, NN / 128);
    build_w_mma_kernel<<<gw, 256, WDYN>>>(S, m_raw);
    dim3 gv(NN / TMW, BB / TMW);
    build_vx_kernel<<<gv, 256>>>(U, b, x);
    solve_kernel<<<SB, 256, DYN_SMEM>>>(out);
}

// round 8
// speedup vs baseline: 3.2954x; 3.2954x over previous
#include <cuda_runtime.h>
#include <cuda_bf16.h>
#include <cuda_fp16.h>
#include <math.h>
#include <stdint.h>

#define NN 2048
#define BB 256
#define DD 512
#define MAXIT 300

// ---- solve: stream W fp16, 32 m-tiles x 4 n-tiles --------------------------
#define SB 128
#define KC 64            // k elements per stage (64 fp16 = 128B rows)
#define NSTG 4
#define MATB (64*128)    // one 64x64 fp16 tile = 8KB
#define STGB (2*MATB)    // A + B
#define O_A 0
#define O_B MATB
#define DYN_SMEM (NSTG*STGB + 128)
#define NKC (NN/KC)      // 32

// ---- build_w tiling --------------------------------------------------------
#define WNSTG 3
#define WMAT (128*128)
#define WSTG (4*WMAT)
#define WDYN (WNSTG*WSTG + 128)

__device__ __half         g_Wh[NN*NN];      // 8MB fp16 W
__device__ __nv_bfloat16  g_Athi[NN*NN];    // A^T splits (for accurate W build)
__device__ __nv_bfloat16  g_Atlo[NN*NN];
__device__ float          g_Vx[NN*BB];      // [i][j]
__device__ __half         g_zh[2][BB*NN];   // fp16 z, [j][k], ping-pong
__device__ double g_nd[3][2];
__device__ unsigned g_arrive, g_release;

__device__ __forceinline__ uint32_t smem_u32(const void* p) {
    uint32_t a;
    asm("{ .reg .u64 t; cvta.to.shared.u64 t, %1; cvt.u32.u64 %0, t; }" : "=r"(a) : "l"(p));
    return a;
}
__device__ __forceinline__ void cp16(uint32_t dst, const void* src) {
    asm volatile("cp.async.cg.shared.global [%0], [%1], 16;" :: "r"(dst), "l"(src) : "memory");
}
#define CP_COMMIT() asm volatile("cp.async.commit_group;" ::: "memory")
#define CP_WAIT(n)  asm volatile("cp.async.wait_group %0;" :: "n"(n) : "memory")
__device__ __forceinline__ void ldsm4(uint32_t* r, uint32_t a) {
    asm volatile("ldmatrix.sync.aligned.m8n8.x4.shared.b16 {%0,%1,%2,%3}, [%4];"
                 : "=r"(r[0]), "=r"(r[1]), "=r"(r[2]), "=r"(r[3]) : "r"(a));
}
__device__ __forceinline__ void mma_bf(float* c, const uint32_t* a, uint32_t b0, uint32_t b1) {
    asm volatile("mma.sync.aligned.m16n8k16.row.col.f32.bf16.bf16.f32 "
                 "{%0,%1,%2,%3}, {%4,%5,%6,%7}, {%8,%9}, {%0,%1,%2,%3};"
                 : "+f"(c[0]), "+f"(c[1]), "+f"(c[2]), "+f"(c[3])
                 : "r"(a[0]), "r"(a[1]), "r"(a[2]), "r"(a[3]), "r"(b0), "r"(b1));
}
__device__ __forceinline__ void mma_hf(float* c, const uint32_t* a, uint32_t b0, uint32_t b1) {
    asm volatile("mma.sync.aligned.m16n8k16.row.col.f32.f16.f16.f32 "
                 "{%0,%1,%2,%3}, {%4,%5,%6,%7}, {%8,%9}, {%0,%1,%2,%3};"
                 : "+f"(c[0]), "+f"(c[1]), "+f"(c[2]), "+f"(c[3])
                 : "r"(a[0]), "r"(a[1]), "r"(a[2]), "r"(a[3]), "r"(b0), "r"(b1));
}

__global__ void init_kernel() {
    int idx = blockIdx.x * blockDim.x + threadIdx.x;
    if (idx < BB * NN) g_zh[0][idx] = __float2half(0.0f);
    if (idx == 0) {
        for (int i = 0; i < 3; i++) { g_nd[i][0] = 0.0; g_nd[i][1] = 0.0; }
        g_arrive = 0u; g_release = 0u;
    }
}

// At[i][k] = A[k][i], split bf16 hi/lo
__global__ void __launch_bounds__(256) split_at_kernel(const float* __restrict__ A) {
    __shared__ float t[32][33];
    const int i0 = blockIdx.x * 32, k0 = blockIdx.y * 32;
    const int lx = threadIdx.x & 31, ly = threadIdx.x >> 5;
#pragma unroll
    for (int r = 0; r < 32; r += 8)
        t[ly + r][lx] = A[(long)(k0 + ly + r) * NN + i0 + lx];
    __syncthreads();
#pragma unroll
    for (int r = 0; r < 32; r += 8) {
        const float v = t[lx][ly + r];
        const long o = (long)(i0 + ly + r) * NN + k0 + lx;
        __nv_bfloat16 hi = __float2bfloat16_rn(v);
        g_Athi[o] = hi;
        g_Atlo[o] = __float2bfloat16_rn(v - __bfloat162float(hi));
    }
}

// W = (1-m)I - At At^T + S - S^T  (bf16x3 mma), output fp16
__global__ void __launch_bounds__(256, 1) build_w_mma_kernel(const float* __restrict__ S,
                                                             const float* __restrict__ m_raw) {
    extern __shared__ __align__(16) char dsm[];
    const uint32_t sbase = (smem_u32(dsm) + 127u) & ~127u;
    const int tid = threadIdx.x, l = tid & 31, warp = tid >> 5;
    const int i0 = blockIdx.x * 128, j0 = blockIdx.y * 128;
    const int wm = (warp >> 2) * 64, wn = (warp & 3) * 32;
    const int r7 = l & 7;
    const int rowA = wm + r7 + ((l >> 3) & 1) * 8;
    const int kgA = (l >> 4) & 1;
    const int rowBb = wn + r7 + ((l >> 4) & 1) * 8;
    const int kgB = (l >> 3) & 1;
    const int ld_r = tid >> 3, ld_c = tid & 7;

    float c[4][4][4];
#pragma unroll
    for (int f = 0; f < 4; f++)
#pragma unroll
        for (int g = 0; g < 4; g++)
#pragma unroll
            for (int q = 0; q < 4; q++) c[f][g][q] = 0.0f;

#define W_LOAD(stg, k0v) do {                                                 \
    const uint32_t sb_ = sbase + (stg) * WSTG;                                \
    _Pragma("unroll")                                                         \
    for (int rep = 0; rep < 4; rep++) {                                       \
        const int r_ = ld_r + rep * 32;                                       \
        const uint32_t d_ = (uint32_t)r_ * 128 + ((uint32_t)(ld_c ^ (r_ & 7)) << 4); \
        const long ga_ = (long)(i0 + r_) * NN + (k0v) + ld_c * 8;             \
        const long gb_ = (long)(j0 + r_) * NN + (k0v) + ld_c * 8;             \
        cp16(sb_ + 0*WMAT + d_, g_Athi + ga_);                                \
        cp16(sb_ + 1*WMAT + d_, g_Atlo + ga_);                                \
        cp16(sb_ + 2*WMAT + d_, g_Athi + gb_);                                \
        cp16(sb_ + 3*WMAT + d_, g_Atlo + gb_);                                \
    } } while (0)

#pragma unroll
    for (int s = 0; s < WNSTG - 1; s++) { W_LOAD(s, s * KC); CP_COMMIT(); }

    for (int kc = 0; kc < NKC; kc++) {
        CP_WAIT(WNSTG - 2);
        __syncthreads();
        if (kc + WNSTG - 1 < NKC) W_LOAD((kc + WNSTG - 1) % WNSTG, (kc + WNSTG - 1) * KC);
        CP_COMMIT();
        const uint32_t sb = sbase + (kc % WNSTG) * WSTG;
#pragma unroll
        for (int s4 = 0; s4 < 4; s4++) {
            const int kg0 = s4 * 2;
            const uint32_t swA = (uint32_t)((kg0 + kgA) ^ r7) << 4;
            const uint32_t swB = (uint32_t)((kg0 + kgB) ^ r7) << 4;
            uint32_t ah[4][4], al[4][4], bh[2][4], bl[2][4];
#pragma unroll
            for (int f = 0; f < 4; f++) {
                ldsm4(ah[f], sb + 0*WMAT + (uint32_t)(rowA + f * 16) * 128 + swA);
                ldsm4(al[f], sb + 1*WMAT + (uint32_t)(rowA + f * 16) * 128 + swA);
            }
#pragma unroll
            for (int g2 = 0; g2 < 2; g2++) {
                ldsm4(bh[g2], sb + 2*WMAT + (uint32_t)(rowBb + g2 * 16) * 128 + swB);
                ldsm4(bl[g2], sb + 3*WMAT + (uint32_t)(rowBb + g2 * 16) * 128 + swB);
            }
#pragma unroll
            for (int f = 0; f < 4; f++)
#pragma unroll
                for (int g2 = 0; g2 < 2; g2++) {
                    mma_bf(c[f][g2*2+0], ah[f], bh[g2][0], bh[g2][1]);
                    mma_bf(c[f][g2*2+1], ah[f], bh[g2][2], bh[g2][3]);
                    mma_bf(c[f][g2*2+0], ah[f], bl[g2][0], bl[g2][1]);
                    mma_bf(c[f][g2*2+1], ah[f], bl[g2][2], bl[g2][3]);
                    mma_bf(c[f][g2*2+0], al[f], bh[g2][0], bh[g2][1]);
                    mma_bf(c[f][g2*2+1], al[f], bh[g2][2], bh[g2][3]);
                }
        }
    }
#undef W_LOAD

    const float m = log1pf(expf(m_raw[0]));
    const float omm = 1.0f - m;
#pragma unroll
    for (int f = 0; f < 4; f++)
#pragma unroll
        for (int g = 0; g < 4; g++)
#pragma unroll
            for (int h = 0; h < 2; h++) {
                const int i = i0 + wm + f * 16 + h * 8 + (l >> 2);
                const int j = j0 + wn + g * 8 + (l & 3) * 2;
                float2 sij = *(const float2*)&S[(long)i * NN + j];
                float w0 = -c[f][g][h*2+0] + sij.x - S[(long)j * NN + i];
                float w1 = -c[f][g][h*2+1] + sij.y - S[(long)(j + 1) * NN + i];
                if (i == j) w0 += omm;
                if (i == j + 1) w1 += omm;
                *(__half2*)&g_Wh[(long)i * NN + j] = __floats2half2_rn(w0, w1);
            }
}

#define TMW 64
#define KTW 16
#define PADW 68
__global__ void __launch_bounds__(256) build_vx_kernel(const float* __restrict__ U,
                                                       const float* __restrict__ b,
                                                       const float* __restrict__ x) {
    __shared__ __align__(16) float Us[KTW][PADW];
    __shared__ __align__(16) float Xs[KTW][PADW];
    const int i0 = blockIdx.x * TMW, j0 = blockIdx.y * TMW;
    const int tx = threadIdx.x & 15, ty = threadIdx.x >> 4;
    float acc[4][4];
#pragma unroll
    for (int a = 0; a < 4; a++)
#pragma unroll
        for (int cc = 0; cc < 4; cc++) acc[a][cc] = 0.0f;
    for (int k0 = 0; k0 < DD; k0 += KTW) {
#pragma unroll
        for (int t = threadIdx.x; t < KTW * TMW; t += 256) {
            int rr = t >> 4, cc = t & 15;
            Us[cc][rr] = U[(i0 + rr) * DD + k0 + cc];
            Xs[cc][rr] = x[(j0 + rr) * DD + k0 + cc];
        }
        __syncthreads();
#pragma unroll
        for (int k = 0; k < KTW; k++) {
            float4 av = *(const float4*)&Us[k][ty * 4];
            float4 bv = *(const float4*)&Xs[k][tx * 4];
            float am[4] = {av.x, av.y, av.z, av.w};
            float bn[4] = {bv.x, bv.y, bv.z, bv.w};
#pragma unroll
            for (int mi = 0; mi < 4; mi++)
#pragma unroll
                for (int ni = 0; ni < 4; ni++) acc[mi][ni] += am[mi] * bn[ni];
        }
        __syncthreads();
    }
#pragma unroll
    for (int mi = 0; mi < 4; mi++) {
        const int i = i0 + ty * 4 + mi;
        const float bi = b[i];
#pragma unroll
        for (int ni = 0; ni < 4; ni++)
            g_Vx[i * BB + j0 + tx * 4 + ni] = acc[mi][ni] + bi;
    }
}

__device__ __forceinline__ void grid_barrier(unsigned& gen) {
    __syncthreads();
    if (threadIdx.x == 0) {
        gen++;
        __threadfence();
        unsigned prev = atomicAdd(&g_arrive, 1u);
        if (prev == SB - 1) {
            atomicExch(&g_arrive, 0u);
            __threadfence();
            atomicExch(&g_release, gen);
        } else {
            while (*(volatile unsigned*)&g_release < gen) { }
            __threadfence();
        }
    }
    __syncthreads();
}

// ---------------- persistent fp16 mma.sync FB solver ------------------------
__global__ void __launch_bounds__(256, 1) solve_kernel(float* __restrict__ out) {
    extern __shared__ __align__(16) char dsm[];
    const uint32_t sbase = (smem_u32(dsm) + 127u) & ~127u;
    __shared__ float sredD[8], sredN[8];

    const int tid = threadIdx.x, l = tid & 31, warp = tid >> 5;
    const int i0 = (blockIdx.x >> 2) * 64, j0 = (blockIdx.x & 3) * 64;
    const int wm = (warp >> 2) * 32, wn = (warp & 3) * 16;
    const int r7 = l & 7;
    const int rowA0 = wm + r7 + ((l >> 3) & 1) * 8;
    const int kgA = (l >> 4) & 1;
    const int rowB = wn + r7 + ((l >> 4) & 1) * 8;
    const int kgB = (l >> 3) & 1;
    const int ld_r0 = tid >> 3, ld_c = tid & 7;
    const uint32_t ld_s0 = ((uint32_t)(ld_c ^ (ld_r0 & 7))) << 4;
    const int ld_r1 = ld_r0 + 32;
    const uint32_t ld_s1 = ((uint32_t)(ld_c ^ (ld_r1 & 7))) << 4;

    float zr[2][2][2][2], vx[2][2][2][2];
#pragma unroll
    for (int f = 0; f < 2; f++)
#pragma unroll
        for (int g = 0; g < 2; g++)
#pragma unroll
            for (int h = 0; h < 2; h++) {
                const int i = i0 + wm + f * 16 + h * 8 + (l >> 2);
                const int j = j0 + wn + g * 8 + (l & 3) * 2;
                float2 v = *(const float2*)&g_Vx[i * BB + j];
                vx[f][g][h][0] = v.x; vx[f][g][h][1] = v.y;
                zr[f][g][h][0] = 0.0f; zr[f][g][h][1] = 0.0f;
            }

#define S_LOAD(stg, k0v, zp) do {                                             \
    const uint32_t sb_ = sbase + (stg) * STGB;                                \
    const long gW0_ = (long)(i0 + ld_r0) * NN + (k0v) + ld_c * 8;             \
    const long gW1_ = (long)(i0 + ld_r1) * NN + (k0v) + ld_c * 8;             \
    const long gZ0_ = (long)(j0 + ld_r0) * NN + (k0v) + ld_c * 8;             \
    const long gZ1_ = (long)(j0 + ld_r1) * NN + (k0v) + ld_c * 8;             \
    const uint32_t d0_ = (uint32_t)ld_r0 * 128 + ld_s0;                       \
    const uint32_t d1_ = (uint32_t)ld_r1 * 128 + ld_s1;                       \
    cp16(sb_ + O_A + d0_, g_Wh + gW0_);                                       \
    cp16(sb_ + O_A + d1_, g_Wh + gW1_);                                       \
    cp16(sb_ + O_B + d0_, (zp) + gZ0_);                                       \
    cp16(sb_ + O_B + d1_, (zp) + gZ1_);                                       \
    } while (0)

    unsigned gen = 0;
    int cur = 0, it = 0;

    while (1) {
        it++;
        const __half* __restrict__ zp = g_zh[cur];
        float c[2][2][4];
#pragma unroll
        for (int f = 0; f < 2; f++)
#pragma unroll
            for (int g = 0; g < 2; g++)
#pragma unroll
                for (int q = 0; q < 4; q++) c[f][g][q] = 0.0f;

#pragma unroll
        for (int s = 0; s < NSTG - 1; s++) { S_LOAD(s, s * KC, zp); CP_COMMIT(); }

        for (int kc = 0; kc < NKC; kc++) {
            CP_WAIT(NSTG - 2);
            __syncthreads();
            if (kc + NSTG - 1 < NKC)
                S_LOAD((kc + NSTG - 1) % NSTG, (kc + NSTG - 1) * KC, zp);
            CP_COMMIT();
            const uint32_t sb = sbase + (kc % NSTG) * STGB;
#pragma unroll
            for (int s4 = 0; s4 < 4; s4++) {
                const int kg0 = s4 * 2;
                const uint32_t swA = (uint32_t)((kg0 + kgA) ^ r7) << 4;
                const uint32_t swB = (uint32_t)((kg0 + kgB) ^ r7) << 4;
                uint32_t ah0[4], ah1[4], bh[4];
                ldsm4(ah0, sb + O_A + (uint32_t)rowA0 * 128 + swA);
                ldsm4(ah1, sb + O_A + (uint32_t)(rowA0 + 16) * 128 + swA);
                ldsm4(bh, sb + O_B + (uint32_t)rowB * 128 + swB);
                mma_hf(c[0][0], ah0, bh[0], bh[1]);
                mma_hf(c[0][1], ah0, bh[2], bh[3]);
                mma_hf(c[1][0], ah1, bh[0], bh[1]);
                mma_hf(c[1][1], ah1, bh[2], bh[3]);
            }
        }

        __half* __restrict__ zn = g_zh[cur ^ 1];
        float d2 = 0.0f, n2 = 0.0f;
#pragma unroll
        for (int f = 0; f < 2; f++)
#pragma unroll
            for (int g = 0; g < 2; g++)
#pragma unroll
                for (int h = 0; h < 2; h++) {
                    const int i = i0 + wm + f * 16 + h * 8 + (l >> 2);
                    const int j = j0 + wn + g * 8 + (l & 3) * 2;
#pragma unroll
                    for (int p = 0; p < 2; p++) {
                        const float zv = zr[f][g][h][p];
                        float v = 0.9f * zv + 0.1f * (c[f][g][h*2+p] + vx[f][g][h][p]);
                        float r = v > 0.0f ? v : 0.0f;
                        zr[f][g][h][p] = r;
                        zn[(j + p) * NN + i] = __float2half_rn(r);
                        const float dd = r - zv;
                        d2 += dd * dd;
                        n2 += zv * zv;
                    }
                }
#pragma unroll
        for (int off = 16; off; off >>= 1) {
            d2 += __shfl_xor_sync(0xffffffffu, d2, off);
            n2 += __shfl_xor_sync(0xffffffffu, n2, off);
        }
        if (l == 0) { sredD[warp] = d2; sredN[warp] = n2; }
        __syncthreads();
        const int nb = it % 3;
        if (tid == 0) {
            double Dd = 0.0, Nd = 0.0;
#pragma unroll
            for (int w = 0; w < 8; w++) { Dd += (double)sredD[w]; Nd += (double)sredN[w]; }
            atomicAdd(&g_nd[nb][0], Dd);
            atomicAdd(&g_nd[nb][1], Nd);
        }

        grid_barrier(gen);

        const double Dt = *(volatile double*)&g_nd[nb][0];
        const double Nt = *(volatile double*)&g_nd[nb][1];
        const double err = sqrt(Dt) / (sqrt(Nt) + 1e-12);
        if (blockIdx.x == 0 && tid == 0) {
            const int rb = (it + 2) % 3;
            *(volatile double*)&g_nd[rb][0] = 0.0;
            *(volatile double*)&g_nd[rb][1] = 0.0;
            __threadfence();
        }
        cur ^= 1;
        if (it >= MAXIT || err < 1e-4) break;
    }
#undef S_LOAD

#pragma unroll
    for (int f = 0; f < 2; f++)
#pragma unroll
        for (int g = 0; g < 2; g++)
#pragma unroll
            for (int h = 0; h < 2; h++) {
                const int i = i0 + wm + f * 16 + h * 8 + (l >> 2);
                const int j = j0 + wn + g * 8 + (l & 3) * 2;
                float2 v;
                v.x = zr[f][g][h][0];
                v.y = zr[f][g][h][1];
                *(float2*)&out[i * BB + j] = v;
            }
}

extern "C" void kernel_launch(void* const* d_in, const int* in_sizes, int n_in,
                              void* d_out, int out_size) {
    const float* A     = (const float*)d_in[0];
    const float* S     = (const float*)d_in[1];
    const float* m_raw = (const float*)d_in[2];
    const float* U     = (const float*)d_in[3];
    const float* b     = (const float*)d_in[4];
    const float* x     = (const float*)d_in[5];
    float* out = (float*)d_out;

    cudaFuncSetAttribute(solve_kernel, cudaFuncAttributeMaxDynamicSharedMemorySize, DYN_SMEM);
    cudaFuncSetAttribute(build_w_mma_kernel, cudaFuncAttributeMaxDynamicSharedMemorySize, WDYN);

    init_kernel<<<(BB * NN + 255) / 256, 256>>>();
    dim3 gt(NN / 32, NN / 32);
    split_at_kernel<<<gt, 256>>>(A);
    dim3 gw(NN / 128, NN / 128);
    build_w_mma_kernel<<<gw, 256, WDYN>>>(S, m_raw);
    dim3 gv(NN / TMW, BB / TMW);
    build_vx_kernel<<<gv, 256>>>(U, b, x);
    solve_kernel<<<SB, 256, DYN_SMEM>>>(out);
}